// round 2
// baseline (speedup 1.0000x reference)
#include <cuda_runtime.h>

#define N_NODES 50000
#define N_EDGES 1600000
#define ND 16
#define ED 16
#define HID 64

// Scratch: aggregation buffer (device global; no allocation allowed)
__device__ float g_agg[N_NODES * ND];
__device__ int g_idx64;   // 1 if edge_index is int64, 0 if int32

typedef unsigned long long u64;

// ---- packed f32x2 helpers (sm_100+ only; ptxas never emits these itself) ----
__device__ __forceinline__ u64 pack2(float lo, float hi) {
    u64 r;
    asm("mov.b64 %0, {%1, %2};" : "=l"(r) : "f"(lo), "f"(hi));
    return r;
}
__device__ __forceinline__ u64 ffma2(u64 a, u64 b, u64 c) {
    u64 d;
    asm("fma.rn.f32x2 %0, %1, %2, %3;" : "=l"(d) : "l"(a), "l"(b), "l"(c));
    return d;
}
__device__ __forceinline__ float2 unpack2(u64 v) {
    float2 f;
    asm("mov.b64 {%0, %1}, %2;" : "=f"(f.x), "=f"(f.y) : "l"(v));
    return f;
}

// ---- dtype probe: decide whether edge_index is int64 or int32 ----
// With genuine int64 data, every value is in [0, N_NODES). With int32 data
// reinterpreted as int64, consecutive index pairs combine into huge values
// almost surely within the first few entries. Deterministic for fixed input.
__global__ void probe_kernel(const long long* __restrict__ idx) {
    if (threadIdx.x == 0 && blockIdx.x == 0) {
        int is64 = 1;
        for (int i = 0; i < 4096; i++) {
            long long v = idx[i];
            if (v < 0 || v >= (long long)N_NODES) { is64 = 0; break; }
        }
        g_idx64 = is64;
    }
}

__global__ void zero_agg_kernel() {
    int i = blockIdx.x * blockDim.x + threadIdx.x;
    if (i < N_NODES * ND) g_agg[i] = 0.0f;
}

// ---- edge kernel: fR MLP + scatter-sum ----
// One thread per edge. Weights in SMEM as f32x2 pairs (warp-uniform broadcast).
__global__ __launch_bounds__(256) void edge_kernel(
    const float* __restrict__ x,
    const void*  __restrict__ eidx,
    const float* __restrict__ e,
    const float* __restrict__ W1,   // [48, 64]
    const float* __restrict__ b1,   // [64]
    const float* __restrict__ W2,   // [64, 16]
    const float* __restrict__ b2,   // [16]
    float* __restrict__ e_new)      // [E, 16]
{
    __shared__ u64   sW1[48 * 32];  // row k: 32 pairs covering hidden dim
    __shared__ u64   sW2[64 * 8];   // row j: 8 pairs covering out dim
    __shared__ float sb1[64];
    __shared__ float sb2[16];

    for (int i = threadIdx.x; i < 48 * 32; i += 256) sW1[i] = ((const u64*)W1)[i];
    for (int i = threadIdx.x; i < 64 * 8;  i += 256) sW2[i] = ((const u64*)W2)[i];
    if (threadIdx.x < 64) sb1[threadIdx.x] = b1[threadIdx.x];
    if (threadIdx.x < 16) sb2[threadIdx.x] = b2[threadIdx.x];
    __syncthreads();

    int edge = blockIdx.x * 256 + threadIdx.x;
    if (edge >= N_EDGES) return;

    int src, dst;
    if (g_idx64) {
        const long long* q = (const long long*)eidx;
        src = (int)q[edge];
        dst = (int)q[N_EDGES + edge];
    } else {
        const int* q = (const int*)eidx;
        src = q[edge];
        dst = q[N_EDGES + edge];
    }

    // h = b1
    u64 h[32];
#pragma unroll
    for (int j = 0; j < 32; j++) h[j] = pack2(sb1[2 * j], sb1[2 * j + 1]);

    // Layer 1: in = [x[dst](16), x[src](16), e[edge](16)]
    const float* in0 = x + (size_t)dst * ND;
    const float* in1 = x + (size_t)src * ND;
    const float* in2 = e + (size_t)edge * ED;
    const float* ins[3] = { in0, in1, in2 };
#pragma unroll
    for (int p = 0; p < 3; p++) {
        const float4* v4 = (const float4*)ins[p];
#pragma unroll
        for (int q4 = 0; q4 < 4; q4++) {
            float4 v = v4[q4];
            float vv[4] = { v.x, v.y, v.z, v.w };
#pragma unroll
            for (int kk = 0; kk < 4; kk++) {
                int k = p * 16 + q4 * 4 + kk;
                u64 a = pack2(vv[kk], vv[kk]);
                const u64* wrow = &sW1[k * 32];
#pragma unroll
                for (int j = 0; j < 32; j++) h[j] = ffma2(a, wrow[j], h[j]);
            }
        }
    }

    // Layer 2: out = relu(h) @ W2 + b2
    u64 out[8];
#pragma unroll
    for (int o = 0; o < 8; o++) out[o] = pack2(sb2[2 * o], sb2[2 * o + 1]);
#pragma unroll
    for (int j = 0; j < 32; j++) {
        float2 hp = unpack2(h[j]);
        float h0 = fmaxf(hp.x, 0.0f);
        float h1 = fmaxf(hp.y, 0.0f);
        u64 a0 = pack2(h0, h0);
        u64 a1 = pack2(h1, h1);
        const u64* w0 = &sW2[(2 * j) * 8];
        const u64* w1 = &sW2[(2 * j + 1) * 8];
#pragma unroll
        for (int o = 0; o < 8; o++) out[o] = ffma2(a0, w0[o], out[o]);
#pragma unroll
        for (int o = 0; o < 8; o++) out[o] = ffma2(a1, w1[o], out[o]);
    }

    float res[16];
#pragma unroll
    for (int o = 0; o < 8; o++) {
        float2 f = unpack2(out[o]);
        res[2 * o] = f.x;
        res[2 * o + 1] = f.y;
    }

    // write e_new + vectorized scatter-add into g_agg[dst]
    float4* eout = (float4*)(e_new + (size_t)edge * ED);
    float*  aggp = g_agg + (size_t)dst * ND;
#pragma unroll
    for (int q4 = 0; q4 < 4; q4++) {
        float4 v = make_float4(res[4 * q4], res[4 * q4 + 1], res[4 * q4 + 2], res[4 * q4 + 3]);
        eout[q4] = v;
        asm volatile("red.global.add.v4.f32 [%0], {%1, %2, %3, %4};"
                     :: "l"(aggp + 4 * q4), "f"(v.x), "f"(v.y), "f"(v.z), "f"(v.w)
                     : "memory");
    }
}

// ---- node kernel: fO MLP ----
__global__ __launch_bounds__(256) void node_kernel(
    const float* __restrict__ x,
    const float* __restrict__ W1,   // [32, 64]
    const float* __restrict__ b1,   // [64]
    const float* __restrict__ W2,   // [64, 16]
    const float* __restrict__ b2,   // [16]
    float* __restrict__ x_new)      // [N, 16]
{
    __shared__ u64   sW1[32 * 32];
    __shared__ u64   sW2[64 * 8];
    __shared__ float sb1[64];
    __shared__ float sb2[16];

    for (int i = threadIdx.x; i < 32 * 32; i += 256) sW1[i] = ((const u64*)W1)[i];
    for (int i = threadIdx.x; i < 64 * 8;  i += 256) sW2[i] = ((const u64*)W2)[i];
    if (threadIdx.x < 64) sb1[threadIdx.x] = b1[threadIdx.x];
    if (threadIdx.x < 16) sb2[threadIdx.x] = b2[threadIdx.x];
    __syncthreads();

    int node = blockIdx.x * 256 + threadIdx.x;
    if (node >= N_NODES) return;

    u64 h[32];
#pragma unroll
    for (int j = 0; j < 32; j++) h[j] = pack2(sb1[2 * j], sb1[2 * j + 1]);

    const float* in0 = x + (size_t)node * ND;
    const float* in1 = g_agg + (size_t)node * ND;
    const float* ins[2] = { in0, in1 };
#pragma unroll
    for (int p = 0; p < 2; p++) {
        const float4* v4 = (const float4*)ins[p];
#pragma unroll
        for (int q4 = 0; q4 < 4; q4++) {
            float4 v = v4[q4];
            float vv[4] = { v.x, v.y, v.z, v.w };
#pragma unroll
            for (int kk = 0; kk < 4; kk++) {
                int k = p * 16 + q4 * 4 + kk;
                u64 a = pack2(vv[kk], vv[kk]);
                const u64* wrow = &sW1[k * 32];
#pragma unroll
                for (int j = 0; j < 32; j++) h[j] = ffma2(a, wrow[j], h[j]);
            }
        }
    }

    u64 out[8];
#pragma unroll
    for (int o = 0; o < 8; o++) out[o] = pack2(sb2[2 * o], sb2[2 * o + 1]);
#pragma unroll
    for (int j = 0; j < 32; j++) {
        float2 hp = unpack2(h[j]);
        float h0 = fmaxf(hp.x, 0.0f);
        float h1 = fmaxf(hp.y, 0.0f);
        u64 a0 = pack2(h0, h0);
        u64 a1 = pack2(h1, h1);
        const u64* w0 = &sW2[(2 * j) * 8];
        const u64* w1 = &sW2[(2 * j + 1) * 8];
#pragma unroll
        for (int o = 0; o < 8; o++) out[o] = ffma2(a0, w0[o], out[o]);
#pragma unroll
        for (int o = 0; o < 8; o++) out[o] = ffma2(a1, w1[o], out[o]);
    }

    float4* xo = (float4*)(x_new + (size_t)node * ND);
#pragma unroll
    for (int o = 0; o < 4; o++) {
        float2 f0 = unpack2(out[2 * o]);
        float2 f1 = unpack2(out[2 * o + 1]);
        xo[o] = make_float4(f0.x, f0.y, f1.x, f1.y);
    }
}

extern "C" void kernel_launch(void* const* d_in, const int* in_sizes, int n_in,
                              void* d_out, int out_size) {
    const float* x      = (const float*)d_in[0];
    const void*  eidx   = d_in[1];
    const float* e      = (const float*)d_in[2];
    const float* fR_W1  = (const float*)d_in[3];
    const float* fR_b1  = (const float*)d_in[4];
    const float* fR_W2  = (const float*)d_in[5];
    const float* fR_b2  = (const float*)d_in[6];
    const float* fO_W1  = (const float*)d_in[7];
    const float* fO_b1  = (const float*)d_in[8];
    const float* fO_W2  = (const float*)d_in[9];
    const float* fO_b2  = (const float*)d_in[10];

    // Output layout: tuple (x_new [N,16], e_new [E,16]) flattened in order.
    float* x_new = (float*)d_out;
    float* e_new = (float*)d_out + (size_t)N_NODES * ND;

    probe_kernel<<<1, 32>>>((const long long*)eidx);
    zero_agg_kernel<<<(N_NODES * ND + 255) / 256, 256>>>();
    edge_kernel<<<N_EDGES / 256, 256>>>(x, eidx, e, fR_W1, fR_b1, fR_W2, fR_b2, e_new);
    node_kernel<<<(N_NODES + 255) / 256, 256>>>(x, fO_W1, fO_b1, fO_W2, fO_b2, x_new);
}

// round 8
// speedup vs baseline: 1.4342x; 1.4342x over previous
#include <cuda_runtime.h>
#include <cstdint>

#define N_NODES 50000
#define N_EDGES 1600000
#define ND 16
#define ED 16
#define HID 64

typedef unsigned long long u64;
typedef unsigned int u32;

// Scratch (no allocation allowed)
__device__ float g_agg[N_NODES * ND];
__device__ int g_idx64;

// ---- packed f32x2 helpers ----
__device__ __forceinline__ u64 pack2(float lo, float hi) {
    u64 r; asm("mov.b64 %0, {%1, %2};" : "=l"(r) : "f"(lo), "f"(hi)); return r;
}
__device__ __forceinline__ u64 ffma2(u64 a, u64 b, u64 c) {
    u64 d; asm("fma.rn.f32x2 %0, %1, %2, %3;" : "=l"(d) : "l"(a), "l"(b), "l"(c)); return d;
}
__device__ __forceinline__ float2 unpack2(u64 v) {
    float2 f; asm("mov.b64 {%0, %1}, %2;" : "=f"(f.x), "=f"(f.y) : "l"(v)); return f;
}

// ---- dtype probe (int64 vs int32 edge_index) ----
__global__ void probe_kernel(const long long* __restrict__ idx) {
    if (threadIdx.x == 0 && blockIdx.x == 0) {
        int is64 = 1;
        for (int i = 0; i < 4096; i++) {
            long long v = idx[i];
            if (v < 0 || v >= (long long)N_NODES) { is64 = 0; break; }
        }
        g_idx64 = is64;
    }
}

__global__ void zero_agg_kernel() {
    int i = blockIdx.x * blockDim.x + threadIdx.x;
    if (i < N_NODES * ND) g_agg[i] = 0.0f;
}

// ---- edge kernel: fR MLP, 2 edges per thread, LDS.128 weight loads ----
// Layer 1 issue mix per k: 16 LDS.128 + 64 FFMA2 (128 MAC) -> fma-pipe bound.
__global__ __launch_bounds__(128) void edge2_kernel(
    const float* __restrict__ x,
    const void*  __restrict__ eidx,
    const float* __restrict__ e,
    const float* __restrict__ W1,   // [48, 64]
    const float* __restrict__ b1,   // [64]
    const float* __restrict__ W2,   // [64, 16]
    const float* __restrict__ b2,   // [16]
    float* __restrict__ e_new)      // [E, 16]
{
    __shared__ ulonglong2 sW1[48 * 16];  // row k: 16 x (2 u64 pairs) covering hidden 64
    __shared__ ulonglong2 sW2[64 * 4];   // row j: 4 x (2 u64 pairs) covering out 16
    __shared__ float sb1[64];
    __shared__ float sb2[16];

    int tid = threadIdx.x;
    for (int i = tid; i < 48 * 16; i += 128) sW1[i] = ((const ulonglong2*)W1)[i];
    for (int i = tid; i < 64 * 4;  i += 128) sW2[i] = ((const ulonglong2*)W2)[i];
    if (tid < 64) sb1[tid] = b1[tid];
    if (tid < 16) sb2[tid] = b2[tid];
    __syncthreads();

    int e0 = blockIdx.x * 256 + tid;
    int e1 = e0 + 128;

    int s0, d0, s1, d1;
    if (g_idx64) {
        const long long* q = (const long long*)eidx;
        s0 = (int)q[e0]; d0 = (int)q[N_EDGES + e0];
        s1 = (int)q[e1]; d1 = (int)q[N_EDGES + e1];
    } else {
        const int* q = (const int*)eidx;
        s0 = q[e0]; d0 = q[N_EDGES + e0];
        s1 = q[e1]; d1 = q[N_EDGES + e1];
    }

    // h accumulators for both edges (pairs over hidden dim)
    u64 h0[32], h1[32];
#pragma unroll
    for (int j = 0; j < 32; j++) {
        u64 b = pack2(sb1[2 * j], sb1[2 * j + 1]);
        h0[j] = b; h1[j] = b;
    }

    const float4* segs0[3] = {
        (const float4*)(x + (size_t)d0 * ND),
        (const float4*)(x + (size_t)s0 * ND),
        (const float4*)(e + (size_t)e0 * ED) };
    const float4* segs1[3] = {
        (const float4*)(x + (size_t)d1 * ND),
        (const float4*)(x + (size_t)s1 * ND),
        (const float4*)(e + (size_t)e1 * ED) };

#pragma unroll
    for (int p = 0; p < 3; p++) {
#pragma unroll
        for (int q4 = 0; q4 < 4; q4++) {
            float4 v0 = segs0[p][q4];
            float4 v1 = segs1[p][q4];
            float a0v[4] = { v0.x, v0.y, v0.z, v0.w };
            float a1v[4] = { v1.x, v1.y, v1.z, v1.w };
#pragma unroll
            for (int kk = 0; kk < 4; kk++) {
                int k = p * 16 + q4 * 4 + kk;
                u64 a0 = pack2(a0v[kk], a0v[kk]);
                u64 a1 = pack2(a1v[kk], a1v[kk]);
                const ulonglong2* wrow = &sW1[k * 16];
#pragma unroll
                for (int jq = 0; jq < 16; jq++) {
                    ulonglong2 w = wrow[jq];
                    h0[2 * jq]     = ffma2(a0, w.x, h0[2 * jq]);
                    h0[2 * jq + 1] = ffma2(a0, w.y, h0[2 * jq + 1]);
                    h1[2 * jq]     = ffma2(a1, w.x, h1[2 * jq]);
                    h1[2 * jq + 1] = ffma2(a1, w.y, h1[2 * jq + 1]);
                }
            }
        }
    }

    // Layer 2: out = relu(h) @ W2 + b2  (both edges)
    u64 o0[8], o1[8];
#pragma unroll
    for (int o = 0; o < 8; o++) {
        u64 b = pack2(sb2[2 * o], sb2[2 * o + 1]);
        o0[o] = b; o1[o] = b;
    }
#pragma unroll
    for (int jp = 0; jp < 32; jp++) {
        float2 p0 = unpack2(h0[jp]);
        float2 p1 = unpack2(h1[jp]);
        float hA0 = fmaxf(p0.x, 0.0f), hB0 = fmaxf(p0.y, 0.0f);
        float hA1 = fmaxf(p1.x, 0.0f), hB1 = fmaxf(p1.y, 0.0f);
        u64 aA0 = pack2(hA0, hA0), aB0 = pack2(hB0, hB0);
        u64 aA1 = pack2(hA1, hA1), aB1 = pack2(hB1, hB1);
        const ulonglong2* wrA = &sW2[(2 * jp) * 4];
        const ulonglong2* wrB = &sW2[(2 * jp + 1) * 4];
#pragma unroll
        for (int oq = 0; oq < 4; oq++) {
            ulonglong2 w = wrA[oq];
            o0[2 * oq]     = ffma2(aA0, w.x, o0[2 * oq]);
            o0[2 * oq + 1] = ffma2(aA0, w.y, o0[2 * oq + 1]);
            o1[2 * oq]     = ffma2(aA1, w.x, o1[2 * oq]);
            o1[2 * oq + 1] = ffma2(aA1, w.y, o1[2 * oq + 1]);
        }
#pragma unroll
        for (int oq = 0; oq < 4; oq++) {
            ulonglong2 w = wrB[oq];
            o0[2 * oq]     = ffma2(aB0, w.x, o0[2 * oq]);
            o0[2 * oq + 1] = ffma2(aB0, w.y, o0[2 * oq + 1]);
            o1[2 * oq]     = ffma2(aB1, w.x, o1[2 * oq]);
            o1[2 * oq + 1] = ffma2(aB1, w.y, o1[2 * oq + 1]);
        }
    }

    // stores + scatter-add for edge 0
    {
        float res[16];
#pragma unroll
        for (int o = 0; o < 8; o++) {
            float2 f = unpack2(o0[o]);
            res[2 * o] = f.x; res[2 * o + 1] = f.y;
        }
        float4* eout = (float4*)(e_new + (size_t)e0 * ED);
        float*  aggp = g_agg + (size_t)d0 * ND;
#pragma unroll
        for (int q4 = 0; q4 < 4; q4++) {
            float4 v = make_float4(res[4 * q4], res[4 * q4 + 1], res[4 * q4 + 2], res[4 * q4 + 3]);
            eout[q4] = v;
            asm volatile("red.global.add.v4.f32 [%0], {%1, %2, %3, %4};"
                         :: "l"(aggp + 4 * q4), "f"(v.x), "f"(v.y), "f"(v.z), "f"(v.w)
                         : "memory");
        }
    }
    // stores + scatter-add for edge 1
    {
        float res[16];
#pragma unroll
        for (int o = 0; o < 8; o++) {
            float2 f = unpack2(o1[o]);
            res[2 * o] = f.x; res[2 * o + 1] = f.y;
        }
        float4* eout = (float4*)(e_new + (size_t)e1 * ED);
        float*  aggp = g_agg + (size_t)d1 * ND;
#pragma unroll
        for (int q4 = 0; q4 < 4; q4++) {
            float4 v = make_float4(res[4 * q4], res[4 * q4 + 1], res[4 * q4 + 2], res[4 * q4 + 3]);
            eout[q4] = v;
            asm volatile("red.global.add.v4.f32 [%0], {%1, %2, %3, %4};"
                         :: "l"(aggp + 4 * q4), "f"(v.x), "f"(v.y), "f"(v.z), "f"(v.w)
                         : "memory");
        }
    }
}

// ---- node kernel: fO MLP (ulonglong2 weight loads) ----
__global__ __launch_bounds__(256) void node_kernel(
    const float* __restrict__ x,
    const float* __restrict__ W1,   // [32, 64]
    const float* __restrict__ b1,   // [64]
    const float* __restrict__ W2,   // [64, 16]
    const float* __restrict__ b2,   // [16]
    float* __restrict__ x_new)      // [N, 16]
{
    __shared__ ulonglong2 sW1[32 * 16];
    __shared__ ulonglong2 sW2[64 * 4];
    __shared__ float sb1[64];
    __shared__ float sb2[16];

    for (int i = threadIdx.x; i < 32 * 16; i += 256) sW1[i] = ((const ulonglong2*)W1)[i];
    for (int i = threadIdx.x; i < 64 * 4;  i += 256) sW2[i] = ((const ulonglong2*)W2)[i];
    if (threadIdx.x < 64) sb1[threadIdx.x] = b1[threadIdx.x];
    if (threadIdx.x < 16) sb2[threadIdx.x] = b2[threadIdx.x];
    __syncthreads();

    int node = blockIdx.x * 256 + threadIdx.x;
    if (node >= N_NODES) return;

    u64 h[32];
#pragma unroll
    for (int j = 0; j < 32; j++) h[j] = pack2(sb1[2 * j], sb1[2 * j + 1]);

    const float4* segs[2] = {
        (const float4*)(x + (size_t)node * ND),
        (const float4*)(g_agg + (size_t)node * ND) };
#pragma unroll
    for (int p = 0; p < 2; p++) {
#pragma unroll
        for (int q4 = 0; q4 < 4; q4++) {
            float4 v = segs[p][q4];
            float vv[4] = { v.x, v.y, v.z, v.w };
#pragma unroll
            for (int kk = 0; kk < 4; kk++) {
                int k = p * 16 + q4 * 4 + kk;
                u64 a = pack2(vv[kk], vv[kk]);
                const ulonglong2* wrow = &sW1[k * 16];
#pragma unroll
                for (int jq = 0; jq < 16; jq++) {
                    ulonglong2 w = wrow[jq];
                    h[2 * jq]     = ffma2(a, w.x, h[2 * jq]);
                    h[2 * jq + 1] = ffma2(a, w.y, h[2 * jq + 1]);
                }
            }
        }
    }

    u64 out[8];
#pragma unroll
    for (int o = 0; o < 8; o++) out[o] = pack2(sb2[2 * o], sb2[2 * o + 1]);
#pragma unroll
    for (int jp = 0; jp < 32; jp++) {
        float2 hp = unpack2(h[jp]);
        float hA = fmaxf(hp.x, 0.0f);
        float hB = fmaxf(hp.y, 0.0f);
        u64 aA = pack2(hA, hA);
        u64 aB = pack2(hB, hB);
        const ulonglong2* wrA = &sW2[(2 * jp) * 4];
        const ulonglong2* wrB = &sW2[(2 * jp + 1) * 4];
#pragma unroll
        for (int oq = 0; oq < 4; oq++) {
            ulonglong2 w = wrA[oq];
            out[2 * oq]     = ffma2(aA, w.x, out[2 * oq]);
            out[2 * oq + 1] = ffma2(aA, w.y, out[2 * oq + 1]);
        }
#pragma unroll
        for (int oq = 0; oq < 4; oq++) {
            ulonglong2 w = wrB[oq];
            out[2 * oq]     = ffma2(aB, w.x, out[2 * oq]);
            out[2 * oq + 1] = ffma2(aB, w.y, out[2 * oq + 1]);
        }
    }

    float4* xo = (float4*)(x_new + (size_t)node * ND);
#pragma unroll
    for (int o = 0; o < 4; o++) {
        float2 f0 = unpack2(out[2 * o]);
        float2 f1 = unpack2(out[2 * o + 1]);
        xo[o] = make_float4(f0.x, f0.y, f1.x, f1.y);
    }
}

extern "C" void kernel_launch(void* const* d_in, const int* in_sizes, int n_in,
                              void* d_out, int out_size) {
    const float* x      = (const float*)d_in[0];
    const void*  eidx   = d_in[1];
    const float* e      = (const float*)d_in[2];
    const float* fR_W1  = (const float*)d_in[3];
    const float* fR_b1  = (const float*)d_in[4];
    const float* fR_W2  = (const float*)d_in[5];
    const float* fR_b2  = (const float*)d_in[6];
    const float* fO_W1  = (const float*)d_in[7];
    const float* fO_b1  = (const float*)d_in[8];
    const float* fO_W2  = (const float*)d_in[9];
    const float* fO_b2  = (const float*)d_in[10];

    float* x_new = (float*)d_out;
    float* e_new = (float*)d_out + (size_t)N_NODES * ND;

    probe_kernel<<<1, 32>>>((const long long*)eidx);
    zero_agg_kernel<<<(N_NODES * ND + 255) / 256, 256>>>();
    edge2_kernel<<<N_EDGES / 256, 128>>>(x, eidx, e, fR_W1, fR_b1, fR_W2, fR_b2, e_new);
    node_kernel<<<(N_NODES + 255) / 256, 256>>>(x, fO_W1, fO_b1, fO_W2, fO_b2, x_new);
}